// round 3
// baseline (speedup 1.0000x reference)
#include <cuda_runtime.h>
#include <float.h>

// Problem constants
#define BB    8
#define NN    4096
#define D_IN  64
#define D_HID 128
#define D_OUT 64
#define MAXD  512   // per-row cap; deg ~ Binom(4096,0.02): mean 83, std 9 -> unreachable

// Scratch (device globals; no runtime allocation allowed)
__device__ float g_h1[BB * NN * D_HID];   // 16 MB
__device__ float g_x2[BB * NN * D_HID];   // 16 MB
__device__ float g_h2[BB * NN * D_OUT];   //  8 MB
__device__ int   g_nbr[NN * MAXD];        //  8 MB
__device__ int   g_deg[NN];

// ---------------------------------------------------------------------------
// Kernel 1: deterministic ELL adjacency build. One block (128 thr) per row.
// Per-thread chunk count -> serial exclusive scan -> ordered write. No atomics,
// fully deterministic, column-sorted.
// ---------------------------------------------------------------------------
__global__ void build_adj_kernel(const float* __restrict__ graph) {
    __shared__ int cnts[129];
    const int row = blockIdx.x;
    const int t   = threadIdx.x;              // 128 threads
    const float* __restrict__ g = graph + (size_t)row * NN;
    const int CH   = NN / 128;                // 32 columns per thread
    const int base = t * CH;

    int c = 0;
    #pragma unroll 8
    for (int j = 0; j < CH; j++) c += (g[base + j] != 0.0f);
    cnts[t + 1] = c;
    __syncthreads();

    if (t == 0) {
        cnts[0] = 0;
        for (int i = 1; i <= 128; i++) cnts[i] += cnts[i - 1];
        g_deg[row] = cnts[128] < MAXD ? cnts[128] : MAXD;
    }
    __syncthreads();

    int off = cnts[t];
    int* __restrict__ nb = g_nbr + (size_t)row * MAXD;
    for (int j = 0; j < CH; j++) {
        if (g[base + j] != 0.0f) {
            if (off < MAXD) nb[off] = base + j;
            off++;
        }
    }
}

// ---------------------------------------------------------------------------
// Kernel 2: out[r, h] = sum_k x[r, k] * W[h, k]   (W row-major [H, K])
// blockDim = H threads; TILE_R rows per block. W staged transposed in SMEM
// with +1 pad (conflict-free). x rows staged in SMEM, read warp-broadcast.
// ---------------------------------------------------------------------------
template <int K, int H, int TILE_R>
__global__ void linear_kernel(const float* __restrict__ x,
                              const float* __restrict__ W,
                              float* __restrict__ out) {
    __shared__ float WsT[K * (H + 1)];
    __shared__ float xs[TILE_R * K];
    const int t = threadIdx.x;                // 0..H-1  (output column)

    for (int i = t; i < K * H; i += H) {
        int h = i / K, k = i % K;
        WsT[k * (H + 1) + h] = W[i];
    }
    const size_t row0 = (size_t)blockIdx.x * TILE_R;
    const float* __restrict__ xp = x + row0 * K;
    for (int i = t; i < TILE_R * K; i += H) xs[i] = xp[i];
    __syncthreads();

    float acc[TILE_R];
    #pragma unroll
    for (int r = 0; r < TILE_R; r++) acc[r] = 0.0f;

    #pragma unroll 4
    for (int k = 0; k < K; k++) {
        const float wk = WsT[k * (H + 1) + t];
        #pragma unroll
        for (int r = 0; r < TILE_R; r++) acc[r] += xs[r * K + k] * wk;
    }

    float* __restrict__ op = out + row0 * H + t;
    #pragma unroll
    for (int r = 0; r < TILE_R; r++) op[(size_t)r * H] = acc[r];
}

// ---------------------------------------------------------------------------
// Kernel 3/5: sparse masked attention, online (flash-style) softmax.
// One warp per (batch, node); warp = 4 independent 8-lane groups, group g owns
// edges e == g (mod 4) with its OWN (m, l, acc) state -> 4x ILP on the softmax
// chain and 7x fewer shfls than a 32-lane reduce. Lane r of a group owns
// feature elems {j*32 + r*4 .. +3}, so each vector-load instruction covers
// 4 x 128B contiguous segments (one neighbor row per group).
// Branchless rescale update -> zero intra-warp divergence in the hot loop.
// Groups merged once at the end via xor-8/16 shuffles.
// ---------------------------------------------------------------------------
template <int D, bool RELU>
__global__ void __launch_bounds__(256)
attn_kernel(const float* __restrict__ h,
            const float* __restrict__ bias,
            float* __restrict__ out) {
    constexpr int NV4 = D / 32;               // float4s per lane: 4 (D=128) / 2 (D=64)
    const int gw   = (blockIdx.x * blockDim.x + threadIdx.x) >> 5;
    const int lane = threadIdx.x & 31;
    const int r    = lane & 7;
    const int g    = lane >> 3;
    const int b    = gw >> 12;                // / NN
    const int n    = gw & (NN - 1);

    const float* __restrict__ hb = h + (size_t)b * NN * D;

    float4 q4[NV4], acc[NV4];
    {
        const float* qp = hb + (size_t)n * D + r * 4;
        #pragma unroll
        for (int j = 0; j < NV4; j++) {
            q4[j]  = *reinterpret_cast<const float4*>(qp + j * 32);
            acc[j] = make_float4(0.f, 0.f, 0.f, 0.f);
        }
    }

    const int deg = g_deg[n];
    const int* __restrict__ nb = g_nbr + (size_t)n * MAXD;
    const unsigned gmask = 0xFFu << (g * 8);

    float mrun = -FLT_MAX;
    float lsum = 0.0f;

    for (int e = g; e < deg; e += 4) {
        const int m = nb[e];
        const float* hp = hb + (size_t)m * D + r * 4;
        float4 hv[NV4];
        #pragma unroll
        for (int j = 0; j < NV4; j++)
            hv[j] = *reinterpret_cast<const float4*>(hp + j * 32);

        float s = 0.0f;
        #pragma unroll
        for (int j = 0; j < NV4; j++)
            s += q4[j].x * hv[j].x + q4[j].y * hv[j].y
               + q4[j].z * hv[j].z + q4[j].w * hv[j].w;
        s += __shfl_xor_sync(gmask, s, 1);
        s += __shfl_xor_sync(gmask, s, 2);
        s += __shfl_xor_sync(gmask, s, 4);

        // branchless online-softmax update
        const float mnew = fmaxf(mrun, s);
        const float corr = __expf(mrun - mnew);  // first edge: exp(-huge) = 0
        const float w    = __expf(s - mnew);
        mrun = mnew;
        lsum = lsum * corr + w;
        #pragma unroll
        for (int j = 0; j < NV4; j++) {
            acc[j].x = acc[j].x * corr + w * hv[j].x;
            acc[j].y = acc[j].y * corr + w * hv[j].y;
            acc[j].z = acc[j].z * corr + w * hv[j].z;
            acc[j].w = acc[j].w * corr + w * hv[j].w;
        }
    }
    __syncwarp();

    // ---- merge the 4 group states ----
    float M = mrun;
    M = fmaxf(M, __shfl_xor_sync(0xffffffffu, M, 8));
    M = fmaxf(M, __shfl_xor_sync(0xffffffffu, M, 16));
    // empty group (mrun=-FLT_MAX): sc = 0. deg >= 1 (self loop) so M is finite.
    const float sc = __expf(mrun - M);
    lsum *= sc;
    #pragma unroll
    for (int j = 0; j < NV4; j++) {
        acc[j].x *= sc; acc[j].y *= sc; acc[j].z *= sc; acc[j].w *= sc;
    }
    lsum += __shfl_xor_sync(0xffffffffu, lsum, 8);
    lsum += __shfl_xor_sync(0xffffffffu, lsum, 16);
    #pragma unroll
    for (int j = 0; j < NV4; j++) {
        acc[j].x += __shfl_xor_sync(0xffffffffu, acc[j].x, 8);
        acc[j].x += __shfl_xor_sync(0xffffffffu, acc[j].x, 16);
        acc[j].y += __shfl_xor_sync(0xffffffffu, acc[j].y, 8);
        acc[j].y += __shfl_xor_sync(0xffffffffu, acc[j].y, 16);
        acc[j].z += __shfl_xor_sync(0xffffffffu, acc[j].z, 8);
        acc[j].z += __shfl_xor_sync(0xffffffffu, acc[j].z, 16);
        acc[j].w += __shfl_xor_sync(0xffffffffu, acc[j].w, 8);
        acc[j].w += __shfl_xor_sync(0xffffffffu, acc[j].w, 16);
    }

    const float inv = 1.0f / lsum;             // deg >= 1 -> lsum >= 1 after merge
    if (g == 0) {
        const float* bp = bias + r * 4;
        float* op = out + ((size_t)b * NN + n) * D + r * 4;
        #pragma unroll
        for (int j = 0; j < NV4; j++) {
            const float4 bv = *reinterpret_cast<const float4*>(bp + j * 32);
            float4 o;
            o.x = acc[j].x * inv + bv.x;
            o.y = acc[j].y * inv + bv.y;
            o.z = acc[j].z * inv + bv.z;
            o.w = acc[j].w * inv + bv.w;
            if (RELU) {
                o.x = fmaxf(o.x, 0.f); o.y = fmaxf(o.y, 0.f);
                o.z = fmaxf(o.z, 0.f); o.w = fmaxf(o.w, 0.f);
            }
            *reinterpret_cast<float4*>(op + j * 32) = o;
        }
    }
}

// ---------------------------------------------------------------------------
// Launch: build adjacency -> h1 -> attn1(+b1,relu) -> h2 -> attn2(+b2) -> out
// ---------------------------------------------------------------------------
extern "C" void kernel_launch(void* const* d_in, const int* in_sizes, int n_in,
                              void* d_out, int out_size) {
    const float* x     = (const float*)d_in[0];  // [8,4096,64]
    const float* graph = (const float*)d_in[1];  // [4096,4096]
    const float* W1    = (const float*)d_in[2];  // [128,64]
    const float* b1    = (const float*)d_in[3];  // [128]
    const float* W2    = (const float*)d_in[4];  // [64,128]
    const float* b2    = (const float*)d_in[5];  // [64]
    float* out         = (float*)d_out;          // [8,4096,1,64]

    void *p_h1, *p_x2, *p_h2;
    cudaGetSymbolAddress(&p_h1, g_h1);
    cudaGetSymbolAddress(&p_x2, g_x2);
    cudaGetSymbolAddress(&p_h2, g_h2);
    float* h1 = (float*)p_h1;
    float* x2 = (float*)p_x2;
    float* h2 = (float*)p_h2;

    const int ROWS = BB * NN;                    // 32768

    build_adj_kernel<<<NN, 128>>>(graph);

    linear_kernel<D_IN, D_HID, 16><<<ROWS / 16, D_HID>>>(x, W1, h1);

    attn_kernel<D_HID, true><<<ROWS / 8, 256>>>(h1, b1, x2);

    linear_kernel<D_HID, D_OUT, 16><<<ROWS / 16, D_OUT>>>(x2, W2, h2);

    attn_kernel<D_OUT, false><<<ROWS / 8, 256>>>(h2, b2, out);
}

// round 6
// speedup vs baseline: 1.5740x; 1.5740x over previous
#include <cuda_runtime.h>
#include <float.h>

// Problem constants
#define BB    8
#define NN    4096
#define D_IN  64
#define D_HID 128
#define D_OUT 64
#define MAXD  512   // per-row cap; deg ~ 1+Binom(4095,0.02): mean 83, std 9 -> unreachable

// Scratch (device globals; no runtime allocation allowed)
__device__ float g_h1[BB * NN * D_HID];   // 16 MB
__device__ float g_x2[BB * NN * D_HID];   // 16 MB
__device__ float g_h2[BB * NN * D_OUT];   //  8 MB
__device__ int   g_nbr[NN * MAXD];        //  8 MB
__device__ int   g_deg[NN];
__device__ float g_W1T[D_IN * D_HID];     // [64][128]  W1 transposed
__device__ float g_W2T[D_HID * D_OUT];    // [128][64]  W2 transposed

// ---------------------------------------------------------------------------
// Kernel 1: deterministic ELL adjacency build. One block (128 thr) per row.
// Count phase uses float4 loads (4x fewer LDG); write phase scalar (rare
// hits, L1-resident lines from the count phase).
// ---------------------------------------------------------------------------
__global__ void build_adj_kernel(const float* __restrict__ graph) {
    __shared__ int cnts[129];
    const int row = blockIdx.x;
    const int t   = threadIdx.x;              // 128 threads
    const float* __restrict__ g = graph + (size_t)row * NN;
    const int CH   = NN / 128;                // 32 columns per thread
    const int base = t * CH;

    int c = 0;
    #pragma unroll
    for (int j = 0; j < CH / 4; j++) {
        const float4 v = *reinterpret_cast<const float4*>(g + base + j * 4);
        c += (v.x != 0.0f) + (v.y != 0.0f) + (v.z != 0.0f) + (v.w != 0.0f);
    }
    cnts[t + 1] = c;
    __syncthreads();

    if (t == 0) {
        cnts[0] = 0;
        for (int i = 1; i <= 128; i++) cnts[i] += cnts[i - 1];
        g_deg[row] = cnts[128] < MAXD ? cnts[128] : MAXD;
    }
    __syncthreads();

    int off = cnts[t];
    int* __restrict__ nb = g_nbr + (size_t)row * MAXD;
    #pragma unroll
    for (int j = 0; j < CH / 4; j++) {
        const float4 v = *reinterpret_cast<const float4*>(g + base + j * 4);
        const float vv[4] = {v.x, v.y, v.z, v.w};
        #pragma unroll
        for (int q = 0; q < 4; q++) {
            if (vv[q] != 0.0f) {
                if (off < MAXD) nb[off] = base + j * 4 + q;
                off++;
            }
        }
    }
}

// ---------------------------------------------------------------------------
// Kernel 1b: transpose both weight matrices (tiny one-time cost).
// ---------------------------------------------------------------------------
__global__ void wtrans_kernel(const float* __restrict__ W1,
                              const float* __restrict__ W2) {
    const int t = blockIdx.x * 256 + threadIdx.x;   // 0..8191
    if (t < D_HID * D_IN) {
        const int h = t >> 6, k = t & 63;           // W1 row-major [128][64]
        g_W1T[k * D_HID + h] = W1[t];
    }
    if (t < D_OUT * D_HID) {
        const int n = t >> 7, k = t & 127;          // W2 row-major [64][128]
        g_W2T[k * D_OUT + n] = W2[t];
    }
}

// ---------------------------------------------------------------------------
// Kernel 2: register-tiled SGEMM  out[r][n] = sum_k X[r][k] * WT[k][n]
// BM=64 x BN=64 per block, 128 threads (tx 0..7, ty 0..15); per-thread
// 4 (rows ty+16i, cyclic) x 8 (cols tx*8..+7). Xs stride 68 -> conflict-free
// scalar reads; Ws reads are LDS.128; 32 FFMA per 6 LDS per thread per k.
// ---------------------------------------------------------------------------
#define GBM 64
#define GBN 64
#define GKC 64
#define XS_STRIDE 68   // 64 + 4: keeps float4 alignment, de-conflicts reads

template <int K>
__global__ void __launch_bounds__(128)
gemm_kernel(const float* __restrict__ X,
            const float* __restrict__ WT,   // [K][H] pre-transposed
            const int H,
            float* __restrict__ out) {
    __shared__ float Xs[GBM * XS_STRIDE];   // 17408 B
    __shared__ float Ws[GKC * GBN];         // 16384 B
    const int tx  = threadIdx.x;            // 0..7
    const int ty  = threadIdx.y;            // 0..15
    const int tid = ty * 8 + tx;            // 0..127
    const size_t row0 = (size_t)blockIdx.x * GBM;
    const int n0 = blockIdx.y * GBN;

    float acc[4][8];
    #pragma unroll
    for (int i = 0; i < 4; i++)
        #pragma unroll
        for (int j = 0; j < 8; j++) acc[i][j] = 0.0f;

    for (int kc = 0; kc < K; kc += GKC) {
        // stage X tile: 64 rows x 64 cols = 1024 float4 / 128 thr = 8 each
        const float* xp = X + row0 * K + kc;
        #pragma unroll
        for (int t = 0; t < 8; t++) {
            const int i  = tid + t * 128;
            const int r  = i >> 4;           // 16 float4 per row
            const int c4 = (i & 15) << 2;
            *reinterpret_cast<float4*>(&Xs[r * XS_STRIDE + c4]) =
                *reinterpret_cast<const float4*>(xp + (size_t)r * K + c4);
        }
        // stage W tile: 64 k-rows x 64 cols, natural copy from WT
        const float* wp = WT + (size_t)kc * H + n0;
        #pragma unroll
        for (int t = 0; t < 8; t++) {
            const int i  = tid + t * 128;
            const int r  = i >> 4;
            const int c4 = (i & 15) << 2;
            *reinterpret_cast<float4*>(&Ws[r * GBN + c4]) =
                *reinterpret_cast<const float4*>(wp + (size_t)r * H + c4);
        }
        __syncthreads();

        #pragma unroll 8
        for (int k = 0; k < GKC; k++) {
            float xv[4];
            #pragma unroll
            for (int i = 0; i < 4; i++)
                xv[i] = Xs[(ty + 16 * i) * XS_STRIDE + k];
            const float4 wv0 = *reinterpret_cast<const float4*>(&Ws[k * GBN + tx * 8]);
            const float4 wv1 = *reinterpret_cast<const float4*>(&Ws[k * GBN + tx * 8 + 4]);
            const float wv[8] = {wv0.x, wv0.y, wv0.z, wv0.w,
                                 wv1.x, wv1.y, wv1.z, wv1.w};
            #pragma unroll
            for (int i = 0; i < 4; i++)
                #pragma unroll
                for (int j = 0; j < 8; j++)
                    acc[i][j] += xv[i] * wv[j];
        }
        __syncthreads();
    }

    float* op = out + row0 * H + n0;
    #pragma unroll
    for (int i = 0; i < 4; i++) {
        float* orow = op + (size_t)(ty + 16 * i) * H + tx * 8;
        *reinterpret_cast<float4*>(orow) =
            make_float4(acc[i][0], acc[i][1], acc[i][2], acc[i][3]);
        *reinterpret_cast<float4*>(orow + 4) =
            make_float4(acc[i][4], acc[i][5], acc[i][6], acc[i][7]);
    }
}

// ---------------------------------------------------------------------------
// Kernel 3/5: sparse masked attention, online (flash-style) softmax.
// One warp per (batch, node); 4 independent 8-lane groups; group g owns edges
// e == g (mod 4) with its own (m, l, acc). Branchless rescale update.
// Two-deep pipeline: row for edge e+4 issued from an index fetched a full
// iteration earlier; index for e+8 fetched this iteration -> the index->row
// L2 chain never sits on the loop critical path.
// ---------------------------------------------------------------------------
template <int D, bool RELU>
__global__ void __launch_bounds__(256)
attn_kernel(const float* __restrict__ h,
            const float* __restrict__ bias,
            float* __restrict__ out) {
    constexpr int NV4 = D / 32;               // float4s per lane: 4 (D=128) / 2 (D=64)
    const int gw   = (blockIdx.x * blockDim.x + threadIdx.x) >> 5;
    const int lane = threadIdx.x & 31;
    const int r    = lane & 7;
    const int g    = lane >> 3;
    const int b    = gw >> 12;                // / NN
    const int n    = gw & (NN - 1);

    const float* __restrict__ hb = h + (size_t)b * NN * D;

    float4 q4[NV4], acc[NV4];
    {
        const float* qp = hb + (size_t)n * D + r * 4;
        #pragma unroll
        for (int j = 0; j < NV4; j++) {
            q4[j]  = *reinterpret_cast<const float4*>(qp + j * 32);
            acc[j] = make_float4(0.f, 0.f, 0.f, 0.f);
        }
    }

    const int deg = g_deg[n];
    const int* __restrict__ nb = g_nbr + (size_t)n * MAXD;
    const unsigned gmask = 0xFFu << (g * 8);

    float mrun = -FLT_MAX;
    float lsum = 0.0f;

    // prologue: row for edge g, index for edge g+4
    float4 hv[NV4];
    int idx_next = 0;                         // index of edge e+4
    {
        const int m0 = (g < deg) ? nb[g] : 0;
        const float* hp = hb + (size_t)m0 * D + r * 4;
        #pragma unroll
        for (int j = 0; j < NV4; j++)
            hv[j] = *reinterpret_cast<const float4*>(hp + j * 32);
        idx_next = (g + 4 < deg) ? nb[g + 4] : m0;
    }

    for (int e = g; e < deg; e += 4) {
        // issue row load for e+4 (index already resident)
        float4 hn[NV4];
        {
            const float* hpn = hb + (size_t)idx_next * D + r * 4;
            #pragma unroll
            for (int j = 0; j < NV4; j++)
                hn[j] = *reinterpret_cast<const float4*>(hpn + j * 32);
        }
        // fetch index for e+8
        const int idx_nn = (e + 8 < deg) ? nb[e + 8] : idx_next;

        float s = 0.0f;
        #pragma unroll
        for (int j = 0; j < NV4; j++)
            s += q4[j].x * hv[j].x + q4[j].y * hv[j].y
               + q4[j].z * hv[j].z + q4[j].w * hv[j].w;
        s += __shfl_xor_sync(gmask, s, 1);
        s += __shfl_xor_sync(gmask, s, 2);
        s += __shfl_xor_sync(gmask, s, 4);

        // branchless online-softmax update
        const float mnew = fmaxf(mrun, s);
        const float corr = __expf(mrun - mnew);  // first edge: exp(-huge) = 0
        const float w    = __expf(s - mnew);
        mrun = mnew;
        lsum = lsum * corr + w;
        #pragma unroll
        for (int j = 0; j < NV4; j++) {
            acc[j].x = acc[j].x * corr + w * hv[j].x;
            acc[j].y = acc[j].y * corr + w * hv[j].y;
            acc[j].z = acc[j].z * corr + w * hv[j].z;
            acc[j].w = acc[j].w * corr + w * hv[j].w;
        }
        // rotate pipeline
        idx_next = idx_nn;
        #pragma unroll
        for (int j = 0; j < NV4; j++) hv[j] = hn[j];
    }
    __syncwarp();

    // ---- merge the 4 group states ----
    float M = mrun;
    M = fmaxf(M, __shfl_xor_sync(0xffffffffu, M, 8));
    M = fmaxf(M, __shfl_xor_sync(0xffffffffu, M, 16));
    // empty group (mrun=-FLT_MAX): sc = 0. deg >= 1 (self loop) so M finite.
    const float sc = __expf(mrun - M);
    lsum *= sc;
    #pragma unroll
    for (int j = 0; j < NV4; j++) {
        acc[j].x *= sc; acc[j].y *= sc; acc[j].z *= sc; acc[j].w *= sc;
    }
    lsum += __shfl_xor_sync(0xffffffffu, lsum, 8);
    lsum += __shfl_xor_sync(0xffffffffu, lsum, 16);
    #pragma unroll
    for (int j = 0; j < NV4; j++) {
        acc[j].x += __shfl_xor_sync(0xffffffffu, acc[j].x, 8);
        acc[j].x += __shfl_xor_sync(0xffffffffu, acc[j].x, 16);
        acc[j].y += __shfl_xor_sync(0xffffffffu, acc[j].y, 8);
        acc[j].y += __shfl_xor_sync(0xffffffffu, acc[j].y, 16);
        acc[j].z += __shfl_xor_sync(0xffffffffu, acc[j].z, 8);
        acc[j].z += __shfl_xor_sync(0xffffffffu, acc[j].z, 16);
        acc[j].w += __shfl_xor_sync(0xffffffffu, acc[j].w, 8);
        acc[j].w += __shfl_xor_sync(0xffffffffu, acc[j].w, 16);
    }

    const float inv = 1.0f / lsum;             // deg >= 1 -> lsum >= 1 after merge
    if (g == 0) {
        const float* bp = bias + r * 4;
        float* op = out + ((size_t)b * NN + n) * D + r * 4;
        #pragma unroll
        for (int j = 0; j < NV4; j++) {
            const float4 bv = *reinterpret_cast<const float4*>(bp + j * 32);
            float4 o;
            o.x = acc[j].x * inv + bv.x;
            o.y = acc[j].y * inv + bv.y;
            o.z = acc[j].z * inv + bv.z;
            o.w = acc[j].w * inv + bv.w;
            if (RELU) {
                o.x = fmaxf(o.x, 0.f); o.y = fmaxf(o.y, 0.f);
                o.z = fmaxf(o.z, 0.f); o.w = fmaxf(o.w, 0.f);
            }
            *reinterpret_cast<float4*>(op + j * 32) = o;
        }
    }
}

// ---------------------------------------------------------------------------
// Launch: adj + Wt -> gemm1 -> attn1(+b1,relu) -> gemm2 -> attn2(+b2) -> out
// ---------------------------------------------------------------------------
extern "C" void kernel_launch(void* const* d_in, const int* in_sizes, int n_in,
                              void* d_out, int out_size) {
    const float* x     = (const float*)d_in[0];  // [8,4096,64]
    const float* graph = (const float*)d_in[1];  // [4096,4096]
    const float* W1    = (const float*)d_in[2];  // [128,64]
    const float* b1    = (const float*)d_in[3];  // [128]
    const float* W2    = (const float*)d_in[4];  // [64,128]
    const float* b2    = (const float*)d_in[5];  // [64]
    float* out         = (float*)d_out;          // [8,4096,1,64]

    void *p_h1, *p_x2, *p_h2, *p_w1t, *p_w2t;
    cudaGetSymbolAddress(&p_h1, g_h1);
    cudaGetSymbolAddress(&p_x2, g_x2);
    cudaGetSymbolAddress(&p_h2, g_h2);
    cudaGetSymbolAddress(&p_w1t, g_W1T);
    cudaGetSymbolAddress(&p_w2t, g_W2T);
    float* h1  = (float*)p_h1;
    float* x2  = (float*)p_x2;
    float* h2  = (float*)p_h2;
    float* w1t = (float*)p_w1t;
    float* w2t = (float*)p_w2t;

    const int ROWS = BB * NN;                    // 32768

    build_adj_kernel<<<NN, 128>>>(graph);
    wtrans_kernel<<<32, 256>>>(W1, W2);

    {   // h1 = x @ W1^T   [32768,64] x [64,128]
        dim3 grid(ROWS / GBM, D_HID / GBN);      // (512, 2)
        dim3 block(8, 16);
        gemm_kernel<D_IN><<<grid, block>>>(x, w1t, D_HID, h1);
    }

    attn_kernel<D_HID, true><<<ROWS / 8, 256>>>(h1, b1, x2);

    {   // h2 = x2 @ W2^T  [32768,128] x [128,64]
        dim3 grid(ROWS / GBM, D_OUT / GBN);      // (512, 1)
        dim3 block(8, 16);
        gemm_kernel<D_HID><<<grid, block>>>(x2, w2t, D_OUT, h2);
    }

    attn_kernel<D_OUT, false><<<ROWS / 8, 256>>>(h2, b2, out);
}